// round 3
// baseline (speedup 1.0000x reference)
#include <cuda_runtime.h>
#include <cuda_fp16.h>
#include <math.h>

// ---------------------------------------------------------------------------
// InteractionBlock (SchNet):
//   W(e) = gauss(e) @ Wf2 + bf2   -> 5121-row fp16 LUT, linear interp (fp32 math)
//   rf   = r @ Wa                 -> fp16 output (only consumed by edge kernel)
//   acc  = segment_sum(rf[src] * W(e), dst)   (red.global.add.v4.f32)
//   out  = ssp(acc @ W1 + b1) @ W2 + b2       (fp32 GEMMs, f32x2 FFMA)
// ---------------------------------------------------------------------------

#define NF 128
#define N_GAUSS 64
#define TAB 5121                 // step = 5/5120 = 1/1024
#define MAX_N 50048

static __device__ __half g_rf_h  [MAX_N * NF];
static __device__ float  g_acc   [MAX_N * NF];
static __device__ float  g_h     [MAX_N * NF];
static __device__ __half g_table_h[TAB * NF];

__device__ __forceinline__ float ssp(float x) {
    float ax = fabsf(x);
    float sp = fmaxf(x, 0.0f) + log1pf(__expf(-ax));
    return sp - 0.69314718055994530942f;
}

// packed 2-wide fp32 FMA (Blackwell f32x2 pipe; halves issue slots)
__device__ __forceinline__ void ffma2(float2& d, const float2& a, const float2& b) {
    unsigned long long ud = *reinterpret_cast<const unsigned long long*>(&d);
    unsigned long long ua = *reinterpret_cast<const unsigned long long*>(&a);
    unsigned long long ub = *reinterpret_cast<const unsigned long long*>(&b);
    asm("fma.rn.f32x2 %0, %1, %2, %0;" : "+l"(ud) : "l"(ua), "l"(ub));
    d = *reinterpret_cast<float2*>(&ud);
}

// ---------------------------------------------------------------------------
// LUT build: table[i][f] = bf2[f] + sum_k exp(coeff*(i*h - o_k)^2) * Wf2[k][f]
// ---------------------------------------------------------------------------
__global__ void build_table_kernel(const float* __restrict__ Wf2,
                                   const float* __restrict__ bf2) {
    const float WIDTH = 5.0f / 63.0f;
    const float COEFF = -0.5f / (WIDTH * WIDTH);
    const float HSTEP = 1.0f / 1024.0f;

    int f = threadIdx.x;
    int i = blockIdx.x;
    float ev = (float)i * HSTEP;
    float acc = bf2[f];
#pragma unroll
    for (int k = 0; k < N_GAUSS; k++) {
        float d = ev - (float)k * WIDTH;
        acc += __expf(COEFF * d * d) * Wf2[k * NF + f];
    }
    g_table_h[i * NF + f] = __float2half_rn(acc);
}

__global__ void zero_acc_kernel(int n4) {
    int i = blockIdx.x * blockDim.x + threadIdx.x;
    if (i < n4) ((float4*)g_acc)[i] = make_float4(0.f, 0.f, 0.f, 0.f);
}

// ---------------------------------------------------------------------------
// Edge kernel: warp per edge. fp16 LUT rows + fp16 rf, fp32 interp + red.v4.
// Per edge reads: 3 x 256B (w0,w1,rf) + 12B (e,a)  -> ~780B.
// ---------------------------------------------------------------------------
__global__ void edge_kernel(const float* __restrict__ e,
                            const int2*  __restrict__ a,   // (dst, src)
                            int E) {
    int gid  = blockIdx.x * blockDim.x + threadIdx.x;
    int edge = gid >> 5;
    int lane = threadIdx.x & 31;
    if (edge >= E) return;

    float ev = e[edge];
    int2  pr = a[edge];          // pr.x = dst, pr.y = src

    float u = ev * 1024.0f;
    int   i = (int)u;
    i = max(0, min(i, TAB - 2));
    float fr = u - (float)i;

    const __half* trow = g_table_h + (size_t)i * NF + lane * 4;
    uint2 w0u = *(const uint2*)trow;
    uint2 w1u = *(const uint2*)(trow + NF);
    uint2 rfu = *(const uint2*)(g_rf_h + (size_t)pr.y * NF + lane * 4);

    float2 w0a = __half22float2(*reinterpret_cast<__half2*>(&w0u.x));
    float2 w0b = __half22float2(*reinterpret_cast<__half2*>(&w0u.y));
    float2 w1a = __half22float2(*reinterpret_cast<__half2*>(&w1u.x));
    float2 w1b = __half22float2(*reinterpret_cast<__half2*>(&w1u.y));
    float2 rfa = __half22float2(*reinterpret_cast<__half2*>(&rfu.x));
    float2 rfb = __half22float2(*reinterpret_cast<__half2*>(&rfu.y));

    float4 v;
    v.x = rfa.x * fmaf(fr, w1a.x - w0a.x, w0a.x);
    v.y = rfa.y * fmaf(fr, w1a.y - w0a.y, w0a.y);
    v.z = rfb.x * fmaf(fr, w1b.x - w0b.x, w0b.x);
    v.w = rfb.y * fmaf(fr, w1b.y - w0b.y, w0b.y);

    float* dp = g_acc + (size_t)pr.x * NF + lane * 4;
    asm volatile("red.global.add.v4.f32 [%0], {%1, %2, %3, %4};"
                 :: "l"(dp), "f"(v.x), "f"(v.y), "f"(v.z), "f"(v.w)
                 : "memory");
}

// ---------------------------------------------------------------------------
// SGEMM v2: C[N,128] = act(A[N,128] @ B[128,128] (+ bias))
// 128x128 block tile, BK=16, 256 threads, 8x8 microtile, f32x2 FMAs.
// As2 stores a-values pre-duplicated (a,a) so inner loop is LDS.64 broadcast.
// ---------------------------------------------------------------------------
template <int ACT, bool HAS_BIAS, typename OutT>
__global__ void __launch_bounds__(256, 2)
gemm128_v2(const float* __restrict__ A,
           const float* __restrict__ B,
           const float* __restrict__ bias,
           OutT* __restrict__ C, int N) {
    __shared__ float2 As2[16][129];   // [k][row], padded: stride 258 words
    __shared__ float  Bs[16][128];    // [k][col]

    int tid = threadIdx.x;
    int tx  = tid & 15;      // col group: cols tx*8 .. tx*8+7
    int ty  = tid >> 4;      // row group: rows ty*8 .. ty*8+7
    int rowBase = blockIdx.x * 128;

    float2 acc[8][4];
#pragma unroll
    for (int i = 0; i < 8; i++)
#pragma unroll
        for (int j = 0; j < 4; j++) acc[i][j] = make_float2(0.f, 0.f);

#pragma unroll
    for (int kt = 0; kt < 8; kt++) {
        // A tile: 128 rows x 16 cols -> As2[c][row] duplicated. 512 float4 loads.
#pragma unroll
        for (int j = 0; j < 2; j++) {
            int idx = tid + j * 256;            // 0..511
            int r   = idx >> 2;                 // 0..127
            int c4  = idx & 3;                  // 0..3
            int grow = rowBase + r;
            float4 av = make_float4(0.f, 0.f, 0.f, 0.f);
            if (grow < N)
                av = *(const float4*)(A + (size_t)grow * NF + kt * 16 + c4 * 4);
            As2[c4 * 4 + 0][r] = make_float2(av.x, av.x);
            As2[c4 * 4 + 1][r] = make_float2(av.y, av.y);
            As2[c4 * 4 + 2][r] = make_float2(av.z, av.z);
            As2[c4 * 4 + 3][r] = make_float2(av.w, av.w);
        }
        // B tile: 16 rows x 128 cols. 512 float4 loads.
#pragma unroll
        for (int j = 0; j < 2; j++) {
            int idx = tid + j * 256;            // 0..511
            int br  = idx >> 5;                 // 0..15
            int bc4 = idx & 31;                 // 0..31
            float4 bv = *(const float4*)(B + (size_t)(kt * 16 + br) * NF + bc4 * 4);
            *(float4*)&Bs[br][bc4 * 4] = bv;
        }
        __syncthreads();

#pragma unroll
        for (int k = 0; k < 16; k++) {
            float2 b[4];
            float4 b0 = *(const float4*)&Bs[k][tx * 8];
            float4 b1 = *(const float4*)&Bs[k][tx * 8 + 4];
            b[0] = make_float2(b0.x, b0.y);
            b[1] = make_float2(b0.z, b0.w);
            b[2] = make_float2(b1.x, b1.y);
            b[3] = make_float2(b1.z, b1.w);
#pragma unroll
            for (int i = 0; i < 8; i++) {
                float2 av = As2[k][ty * 8 + i];
#pragma unroll
                for (int j = 0; j < 4; j++) ffma2(acc[i][j], av, b[j]);
            }
        }
        __syncthreads();
    }

    // epilogue
    float bb[8];
#pragma unroll
    for (int j = 0; j < 8; j++) bb[j] = 0.f;
    if (HAS_BIAS) {
        float4 t0 = *(const float4*)(bias + tx * 8);
        float4 t1 = *(const float4*)(bias + tx * 8 + 4);
        bb[0]=t0.x; bb[1]=t0.y; bb[2]=t0.z; bb[3]=t0.w;
        bb[4]=t1.x; bb[5]=t1.y; bb[6]=t1.z; bb[7]=t1.w;
    }

#pragma unroll
    for (int i = 0; i < 8; i++) {
        int row = rowBase + ty * 8 + i;
        if (row >= N) continue;
        float o[8];
#pragma unroll
        for (int j = 0; j < 4; j++) {
            o[2*j]   = acc[i][j].x + bb[2*j];
            o[2*j+1] = acc[i][j].y + bb[2*j+1];
        }
        if (ACT == 1) {
#pragma unroll
            for (int j = 0; j < 8; j++) o[j] = ssp(o[j]);
        }
        if (sizeof(OutT) == 2) {
            __half2* cp = (__half2*)((__half*)C + (size_t)row * NF + tx * 8);
#pragma unroll
            for (int j = 0; j < 4; j++)
                cp[j] = __floats2half2_rn(o[2*j], o[2*j+1]);
        } else {
            float* cp = (float*)C + (size_t)row * NF + tx * 8;
            *(float4*)(cp)     = make_float4(o[0], o[1], o[2], o[3]);
            *(float4*)(cp + 4) = make_float4(o[4], o[5], o[6], o[7]);
        }
    }
}

// ---------------------------------------------------------------------------
// Launch
// ---------------------------------------------------------------------------
extern "C" void kernel_launch(void* const* d_in, const int* in_sizes, int n_in,
                              void* d_out, int out_size) {
    const float* r   = (const float*)d_in[0];
    const float* e   = (const float*)d_in[1];
    const float* Wf2 = (const float*)d_in[2];
    const float* bf2 = (const float*)d_in[3];
    const float* Wa  = (const float*)d_in[4];
    const float* W1  = (const float*)d_in[5];
    const float* b1  = (const float*)d_in[6];
    const float* W2  = (const float*)d_in[7];
    const float* b2  = (const float*)d_in[8];
    const int*   a   = (const int*)d_in[9];

    int N = in_sizes[0] / NF;     // 50000
    int E = in_sizes[1];          // 800000

    __half *p_rf_h;  float *p_acc, *p_h;
    cudaGetSymbolAddress((void**)&p_rf_h, g_rf_h);
    cudaGetSymbolAddress((void**)&p_acc,  g_acc);
    cudaGetSymbolAddress((void**)&p_h,    g_h);

    // 1. Filter LUT (fp16, includes bf2)
    build_table_kernel<<<TAB, 128>>>(Wf2, bf2);

    // 2. Zero scatter accumulator
    int n4 = (N * NF) / 4;
    zero_acc_kernel<<<(n4 + 255) / 256, 256>>>(n4);

    // 3. rf = r @ Wa  (fp16 out)
    int gb = (N + 127) / 128;
    gemm128_v2<0, false, __half><<<gb, 256>>>(r, Wa, nullptr, p_rf_h, N);

    // 4. Edge gather-modulate-scatter
    int eblocks = (E + 7) / 8;
    edge_kernel<<<eblocks, 256>>>(e, (const int2*)a, E);

    // 5. h = ssp(acc @ W1 + b1)
    gemm128_v2<1, true, float><<<gb, 256>>>(p_acc, W1, b1, p_h, N);

    // 6. out = h @ W2 + b2
    gemm128_v2<0, true, float><<<gb, 256>>>(p_h, W2, b2, (float*)d_out, N);
}